// round 15
// baseline (speedup 1.0000x reference)
#include <cuda_runtime.h>
#include <cuda_bf16.h>
#include <cstdint>

// Problem constants
#define B_  64
#define T_  512
#define H_  768
#define S_  128
#define M_  (B_ * S_)          // 8192 rows through the MLP

// GEMM tiling (warp-level mma.sync, fused 3-product split-bf16)
#define BM 128
#define BN 64                      // grid = (768/64) x (8192/128) = 768 CTAs
#define BKC 32                     // bf16 K per chunk
#define NCH (H_ / BKC)             // 24 chunks

// Padded, UN-swizzled smem rows: 32 bf16 data (64B) + 16B pad = 80B.
// Stride 20 words: all 8-row ldmatrix phases / cp.async writes conflict-free.
#define ROWB     80
#define A_TILE   (128 * ROWB)            // 10240 (one of hi/lo)
#define B_TILE   (64 * ROWB)             // 5120
#define OFF_AHI  0
#define OFF_ALO  (A_TILE)
#define OFF_BHI  (2 * A_TILE)
#define OFF_BLO  (2 * A_TILE + B_TILE)
#define STAGE_B  (2 * A_TILE + 2 * B_TILE)   // 30720
#define SMEM_B   (2 * STAGE_B)               // 61440 -> 3 CTAs/SM (184KB)

#define NPART 24                   // head partials: 12 nblk x 2 warp-halves

// Scratch (no allocation allowed -> __device__ globals).
// CRITICAL: referenced ONLY inside device code. Passing a __device__ global as
// a kernel argument from host code passes the HOST shadow symbol's address;
// on GB300 (HMM/ATS) that address is GPU-dereferenceable, so kernels silently
// read zero-filled host .bss -- the R6-R10 failure mode.
__device__ __align__(128) __nv_bfloat16 g_ahi[M_ * H_];
__device__ __align__(128) __nv_bfloat16 g_alo[M_ * H_];
__device__ __align__(128) __nv_bfloat16 g_xhi[M_ * H_];
__device__ __align__(128) __nv_bfloat16 g_xlo[M_ * H_];
__device__ __align__(128) __nv_bfloat16 g_w1hi[H_ * H_];
__device__ __align__(128) __nv_bfloat16 g_w1lo[H_ * H_];
__device__ __align__(128) __nv_bfloat16 g_w2hi[H_ * H_];
__device__ __align__(128) __nv_bfloat16 g_w2lo[H_ * H_];
__device__ __align__(128) float g_dotp[NPART * M_];   // head partial dots

// ---------------------------------------------------------------------------
// Helpers
// ---------------------------------------------------------------------------
__device__ __forceinline__ void cp16(uint32_t smem, const void* gmem)
{
    asm volatile("cp.async.cg.shared.global [%0], [%1], 16;\n"
                 :: "r"(smem), "l"(gmem) : "memory");
}

__device__ __forceinline__ void ldsm_x4(uint32_t* r, uint32_t addr)
{
    asm volatile("ldmatrix.sync.aligned.m8n8.x4.shared.b16 {%0,%1,%2,%3}, [%4];"
                 : "=r"(r[0]), "=r"(r[1]), "=r"(r[2]), "=r"(r[3]) : "r"(addr));
}

__device__ __forceinline__ void mma_bf16(float* d, const uint32_t* a,
                                         uint32_t b0, uint32_t b1)
{
    asm volatile(
        "mma.sync.aligned.m16n8k16.row.col.f32.bf16.bf16.f32 "
        "{%0,%1,%2,%3}, {%4,%5,%6,%7}, {%8,%9}, {%0,%1,%2,%3};"
        : "+f"(d[0]), "+f"(d[1]), "+f"(d[2]), "+f"(d[3])
        : "r"(a[0]), "r"(a[1]), "r"(a[2]), "r"(a[3]), "r"(b0), "r"(b1));
}

__device__ __forceinline__ float gelu_exact(float x)
{
    return 0.5f * x * (1.0f + erff(x * 0.70710678118654752f));
}

__device__ __forceinline__ void split_bf16(float v, __nv_bfloat16& h, __nv_bfloat16& l)
{
    h = __float2bfloat16(v);
    l = __float2bfloat16(v - __bfloat162float(h));
}

// ---------------------------------------------------------------------------
// Kernel 1: per-(batch, statement) mean pooling -> split bf16 (g_ahi/g_alo).
// ---------------------------------------------------------------------------
__global__ __launch_bounds__(256) void pool_kernel(const float* __restrict__ hidden,
                                                   const int*   __restrict__ sids)
{
    const int bs = blockIdx.x;
    const int b  = bs >> 7;
    const int s  = bs & (S_ - 1);

    __shared__ int s_lo, s_hi;
    if (threadIdx.x == 0) {
        const int* ids = sids + b * T_;
        int lo = 0, hi = T_;
        while (lo < hi) { int m = (lo + hi) >> 1; if (ids[m] < s) lo = m + 1; else hi = m; }
        s_lo = lo;
        hi = T_;
        while (lo < hi) { int m = (lo + hi) >> 1; if (ids[m] < s + 1) lo = m + 1; else hi = m; }
        s_hi = lo;
    }
    __syncthreads();

    const int lo  = s_lo;
    const int cnt = s_hi - s_lo;
    const float inv = 1.0f / (float)max(cnt, 1);

    const int c = threadIdx.x;
    float a0 = 0.f, a1 = 0.f, a2 = 0.f;
    const float* row = hidden + ((size_t)b * T_ + lo) * H_;
    for (int t = 0; t < cnt; ++t, row += H_) {
        a0 += row[c];
        a1 += row[c + 256];
        a2 += row[c + 512];
    }
    const size_t o = (size_t)bs * H_;
    __nv_bfloat16 h, l;
    split_bf16(a0 * inv, h, l); g_ahi[o + c]       = h; g_alo[o + c]       = l;
    split_bf16(a1 * inv, h, l); g_ahi[o + c + 256] = h; g_alo[o + c + 256] = l;
    split_bf16(a2 * inv, h, l); g_ahi[o + c + 512] = h; g_alo[o + c + 512] = l;
}

// ---------------------------------------------------------------------------
// Kernel 2: weight transpose + bf16 split.  W[k][n] -> hi/lo[n][k].
// ---------------------------------------------------------------------------
__global__ __launch_bounds__(256) void wsplit_kernel(const float* __restrict__ W,
                                                     int which)
{
    __nv_bfloat16* hi = which ? g_w2hi : g_w1hi;
    __nv_bfloat16* lo = which ? g_w2lo : g_w1lo;

    __shared__ float tile[32][33];
    const int kb = blockIdx.y * 32, nb = blockIdx.x * 32;
    const int tx = threadIdx.x, ty = threadIdx.y;   // 32 x 8

#pragma unroll
    for (int i = ty; i < 32; i += 8)
        tile[i][tx] = W[(size_t)(kb + i) * H_ + nb + tx];
    __syncthreads();
#pragma unroll
    for (int i = ty; i < 32; i += 8) {
        const float v = tile[tx][i];               // W[kb+tx][nb+i]
        const size_t o = (size_t)(nb + i) * H_ + kb + tx;
        __nv_bfloat16 h, l;
        split_bf16(v, h, l);
        hi[o] = h;
        lo[o] = l;
    }
}

// ---------------------------------------------------------------------------
// Kernel 3: fused split-bf16 mma.sync GEMM + bias + exact GELU.
//   acc += Ahi.Bhi + Alo.Bhi + Ahi.Blo  per once-loaded K-chunk (drops Alo.Blo).
// CTA 128x64, 8 warps of 32x32, 3 CTAs/SM (24 warps). Strength-reduced
// cp.async loader (precomputed offsets, no div/mod in the mainloop).
// MODE 0: A=g_ahi/g_alo, B=g_w1*, out split bf16 -> g_xhi/g_xlo.
// MODE 1: A=g_xhi/g_xlo, B=g_w2*, fused head: gelu -> dot w3 -> g_dotp.
// ---------------------------------------------------------------------------
template <int MODE>
__global__ __launch_bounds__(256, 3) void gemm_mma_kernel(const float* __restrict__ bias,
                                                          const float* __restrict__ w3)
{
    const __nv_bfloat16* __restrict__ Ahi = MODE ? g_xhi : g_ahi;
    const __nv_bfloat16* __restrict__ Alo = MODE ? g_xlo : g_alo;
    const __nv_bfloat16* __restrict__ Bhi = MODE ? g_w2hi : g_w1hi;
    const __nv_bfloat16* __restrict__ Blo = MODE ? g_w2lo : g_w1lo;

    extern __shared__ __align__(16) char smem[];
    const uint32_t sb = (uint32_t)__cvta_generic_to_shared(smem);

    const int tid  = threadIdx.x;
    const int wid  = tid >> 5;
    const int lane = tid & 31;
    const int gid  = lane >> 2;
    const int tig  = lane & 3;
    const int m0 = blockIdx.y * BM;
    const int n0 = blockIdx.x * BN;

    // ---- strength-reduced loader state (tile selectors compile-time per i) --
    // A: 2 tiles x 128 rows x 4 cc -> 1024 cp16, 4/thread (i<2: hi, i>=2: lo)
    // B: 2 tiles x  64 rows x 4 cc ->  512 cp16, 2/thread (i==0: hi, i==1: lo)
    uint32_t goffA[4], smoA[4], goffB[2], smoB[2];
#pragma unroll
    for (int i = 0; i < 4; ++i) {
        const int idx = tid + i * 256;
        const int r   = (idx >> 2) & 127;
        const int cc  = idx & 3;
        goffA[i] = (uint32_t)((m0 + r) * H_ + cc * 8);
        smoA[i]  = sb + (i >= 2 ? OFF_ALO : OFF_AHI) + (uint32_t)(r * ROWB + cc * 16);
    }
#pragma unroll
    for (int i = 0; i < 2; ++i) {
        const int idx = tid + i * 256;
        const int r   = (idx >> 2) & 63;
        const int cc  = idx & 3;
        goffB[i] = (uint32_t)((n0 + r) * H_ + cc * 8);
        smoB[i]  = sb + (i ? OFF_BLO : OFF_BHI) + (uint32_t)(r * ROWB + cc * 16);
    }

    auto issue = [&](int kk, uint32_t bufoff) {
        cp16(smoA[0] + bufoff, Ahi + goffA[0] + kk);
        cp16(smoA[1] + bufoff, Ahi + goffA[1] + kk);
        cp16(smoA[2] + bufoff, Alo + goffA[2] + kk);
        cp16(smoA[3] + bufoff, Alo + goffA[3] + kk);
        cp16(smoB[0] + bufoff, Bhi + goffB[0] + kk);
        cp16(smoB[1] + bufoff, Blo + goffB[1] + kk);
        asm volatile("cp.async.commit_group;" ::: "memory");
    };

    // warp tile: 32 (m) x 32 (n);  8 warps = 4m x 2n
    const int wm = (wid & 3) * 32;
    const int wn = (wid >> 2) * 32;

    // ldmatrix.x4 lane addressing (audited): lanes 0-15 -> rows 0-15 byte 0;
    // lanes 16-31 -> rows 0-15 byte 16.
    const int lm_row = lane & 15;
    const int lm_col = (lane >> 4) * 16;
    const uint32_t a_row = (uint32_t)((wm + lm_row) * ROWB) + lm_col;
    const uint32_t b_row = (uint32_t)((wn + lm_row) * ROWB) + lm_col;

    float acc[2][4][4];
#pragma unroll
    for (int i = 0; i < 2; ++i)
#pragma unroll
        for (int j = 0; j < 4; ++j)
#pragma unroll
            for (int k = 0; k < 4; ++k) acc[i][j][k] = 0.f;

    issue(0, 0);
    issue(BKC, STAGE_B);

    // compute on buf (compile-time bufoff), c-loop unrolled by 2
    auto compute = [&](uint32_t bufoff) {
#pragma unroll
        for (int kk2 = 0; kk2 < 2; ++kk2) {
            const uint32_t kb = kk2 * 32;
            uint32_t ahi[2][4], alo[2][4];
            ldsm_x4(ahi[0], sb + bufoff + OFF_AHI + a_row + kb);
            ldsm_x4(ahi[1], sb + bufoff + OFF_AHI + a_row + 16 * ROWB + kb);
            ldsm_x4(alo[0], sb + bufoff + OFF_ALO + a_row + kb);
            ldsm_x4(alo[1], sb + bufoff + OFF_ALO + a_row + 16 * ROWB + kb);
#pragma unroll
            for (int g = 0; g < 2; ++g) {          // n-groups of 16
                uint32_t bh[4], bl[4];
                ldsm_x4(bh, sb + bufoff + OFF_BHI + b_row + (uint32_t)(g * 16 * ROWB) + kb);
                ldsm_x4(bl, sb + bufoff + OFF_BLO + b_row + (uint32_t)(g * 16 * ROWB) + kb);
                // product-major order (chain distance 4)
                mma_bf16(acc[0][2 * g],     ahi[0], bh[0], bh[2]);
                mma_bf16(acc[0][2 * g + 1], ahi[0], bh[1], bh[3]);
                mma_bf16(acc[1][2 * g],     ahi[1], bh[0], bh[2]);
                mma_bf16(acc[1][2 * g + 1], ahi[1], bh[1], bh[3]);

                mma_bf16(acc[0][2 * g],     alo[0], bh[0], bh[2]);
                mma_bf16(acc[0][2 * g + 1], alo[0], bh[1], bh[3]);
                mma_bf16(acc[1][2 * g],     alo[1], bh[0], bh[2]);
                mma_bf16(acc[1][2 * g + 1], alo[1], bh[1], bh[3]);

                mma_bf16(acc[0][2 * g],     ahi[0], bl[0], bl[2]);
                mma_bf16(acc[0][2 * g + 1], ahi[0], bl[1], bl[3]);
                mma_bf16(acc[1][2 * g],     ahi[1], bl[0], bl[2]);
                mma_bf16(acc[1][2 * g + 1], ahi[1], bl[1], bl[3]);
            }
        }
    };

#pragma unroll 1
    for (int c = 0; c < NCH; c += 2) {
        // even chunk: buf 0
        if (c + 1 < NCH) asm volatile("cp.async.wait_group 1;" ::: "memory");
        else             asm volatile("cp.async.wait_group 0;" ::: "memory");
        __syncthreads();
        compute(0);
        __syncthreads();
        if (c + 2 < NCH) issue((c + 2) * BKC, 0);
        // odd chunk: buf 1
        if (c + 2 < NCH) asm volatile("cp.async.wait_group 1;" ::: "memory");
        else             asm volatile("cp.async.wait_group 0;" ::: "memory");
        __syncthreads();
        compute(STAGE_B);
        __syncthreads();
        if (c + 3 < NCH) issue((c + 3) * BKC, STAGE_B);
    }

    // Epilogue: PTX C layout: c0/c1 at (gid, tig*2 /+1), c2/c3 at (gid+8, ...)
#pragma unroll
    for (int mt = 0; mt < 2; ++mt) {
        const int r0 = m0 + wm + mt * 16 + gid;
        float d0 = 0.f, d1 = 0.f;       // MODE 1 head partials (rows r0, r0+8)
#pragma unroll
        for (int nt = 0; nt < 4; ++nt) {
            const int col = n0 + wn + nt * 8 + tig * 2;
            const float bz0 = __ldg(&bias[col]);
            const float bz1 = __ldg(&bias[col + 1]);
            const float* a4 = acc[mt][nt];
            const float v00 = gelu_exact(a4[0] + bz0);
            const float v01 = gelu_exact(a4[1] + bz1);
            const float v10 = gelu_exact(a4[2] + bz0);
            const float v11 = gelu_exact(a4[3] + bz1);
            if (MODE == 0) {
                __nv_bfloat162 h0, l0, h1, l1;
                split_bf16(v00, h0.x, l0.x); split_bf16(v01, h0.y, l0.y);
                split_bf16(v10, h1.x, l1.x); split_bf16(v11, h1.y, l1.y);
                *(__nv_bfloat162*)(g_xhi + (size_t)r0 * H_ + col)       = h0;
                *(__nv_bfloat162*)(g_xlo + (size_t)r0 * H_ + col)       = l0;
                *(__nv_bfloat162*)(g_xhi + (size_t)(r0 + 8) * H_ + col) = h1;
                *(__nv_bfloat162*)(g_xlo + (size_t)(r0 + 8) * H_ + col) = l1;
            } else {
                const float w0 = __ldg(&w3[col]);
                const float w1 = __ldg(&w3[col + 1]);
                d0 += v00 * w0 + v01 * w1;
                d1 += v10 * w0 + v11 * w1;
            }
        }
        if (MODE == 1) {
            d0 += __shfl_xor_sync(0xffffffffu, d0, 1);
            d0 += __shfl_xor_sync(0xffffffffu, d0, 2);
            d1 += __shfl_xor_sync(0xffffffffu, d1, 1);
            d1 += __shfl_xor_sync(0xffffffffu, d1, 2);
            if (tig == 0) {
                const int p = blockIdx.x * 2 + (wid >> 2);   // 0..23
                g_dotp[p * M_ + r0]     = d0;
                g_dotp[p * M_ + r0 + 8] = d1;
            }
        }
    }
}

// ---------------------------------------------------------------------------
// Kernel 4: out[i] = sigmoid(sum_p dotp[p][i] + b3).  Deterministic partials.
// ---------------------------------------------------------------------------
__global__ __launch_bounds__(256) void finalize_kernel(const float* __restrict__ b3,
                                                       float* __restrict__ out)
{
    const int i = blockIdx.x * 256 + threadIdx.x;
    float s = b3[0];
#pragma unroll
    for (int p = 0; p < NPART; ++p) s += g_dotp[p * M_ + i];
    out[i] = 1.0f / (1.0f + expf(-s));
}

// ---------------------------------------------------------------------------
// Launch: wsplit(w1,w2) -> pool -> gemm<0> -> gemm<1> (fused head) -> finalize.
// Only harness-provided d_in/d_out pointers cross the host->kernel boundary;
// all scratch is device-side symbols. Graph-capturable, allocation-free.
// ---------------------------------------------------------------------------
extern "C" void kernel_launch(void* const* d_in, const int* in_sizes, int n_in,
                              void* d_out, int out_size)
{
    const float* hidden = (const float*)d_in[0];
    const int*   sids   = (const int*)  d_in[1];
    const float* w1     = (const float*)d_in[2];
    const float* b1     = (const float*)d_in[3];
    const float* w2     = (const float*)d_in[4];
    const float* b2     = (const float*)d_in[5];
    const float* w3     = (const float*)d_in[6];
    const float* b3     = (const float*)d_in[7];
    float*       out    = (float*)d_out;

    cudaFuncSetAttribute(gemm_mma_kernel<0>,
                         cudaFuncAttributeMaxDynamicSharedMemorySize, SMEM_B);
    cudaFuncSetAttribute(gemm_mma_kernel<1>,
                         cudaFuncAttributeMaxDynamicSharedMemorySize, SMEM_B);

    dim3 wgrid(H_ / 32, H_ / 32);     // (24, 24)
    dim3 wblk(32, 8);
    wsplit_kernel<<<wgrid, wblk>>>(w1, 0);
    wsplit_kernel<<<wgrid, wblk>>>(w2, 1);

    pool_kernel<<<M_, 256>>>(hidden, sids);            // -> g_ahi / g_alo

    dim3 grid(H_ / BN, M_ / BM);                        // (12, 64) = 768 CTAs
    gemm_mma_kernel<0><<<grid, 256, SMEM_B>>>(b1, w3);  // -> g_xhi / g_xlo
    gemm_mma_kernel<1><<<grid, 256, SMEM_B>>>(b2, w3);  // -> g_dotp

    finalize_kernel<<<M_ / 256, 256>>>(b3, out);        // g_dotp -> out
}

// round 16
// speedup vs baseline: 1.3250x; 1.3250x over previous
#include <cuda_runtime.h>
#include <cuda_bf16.h>
#include <cstdint>

// Problem constants
#define B_  64
#define T_  512
#define H_  768
#define S_  128
#define M_  (B_ * S_)          // 8192 rows through the MLP

// GEMM tiling
#define BM 128
#define BN 192                     // grid (4, 64) = 256 CTAs -> single wave @2/SM
#define BKC 32                     // bf16 K per chunk
#define NCH (H_ / BKC)             // 24 chunks
#define NKCH 24

// Tiled scratch layout: each (block,kchunk) tile is CONTIGUOUS in gmem so one
// cp.async.bulk moves it (LDGSTS rt=8cyc/op made 16B cp.async the bottleneck:
// 15.7M ops/GEMM = 213k cyc/SMSP = the entire 117us R13 kernel time).
// A tile: 128 rows x 32 bf16 (64B rows) = 8192 B. B tile: 192 rows = 12288 B.
// In-tile swizzle: 16B-chunk c stored at c ^ ((row>>1)&3) -> all 8-row
// ldmatrix phases hit 8 distinct 16B bank groups (conflict-free).
#define A_T      8192
#define B_T      12288
#define OFF_AHI  0
#define OFF_ALO  8192
#define OFF_BHI  16384
#define OFF_BLO  28672
#define STAGE_B  40960
#define DATA_B   (2 * STAGE_B)     // 81920, double buffered
#define SMEM_B   (DATA_B + 128)    // + mbarriers

#define NPART 8                    // head partials: 4 nblk x 2 warp-halves

// Scratch (no allocation allowed -> __device__ globals).
// CRITICAL: referenced ONLY inside device code (host-shadow/ATS trap, R6-R10).
__device__ __align__(128) __nv_bfloat16 g_ahi[M_ * H_];
__device__ __align__(128) __nv_bfloat16 g_alo[M_ * H_];
__device__ __align__(128) __nv_bfloat16 g_xhi[M_ * H_];
__device__ __align__(128) __nv_bfloat16 g_xlo[M_ * H_];
__device__ __align__(128) __nv_bfloat16 g_w1hi[H_ * H_];
__device__ __align__(128) __nv_bfloat16 g_w1lo[H_ * H_];
__device__ __align__(128) __nv_bfloat16 g_w2hi[H_ * H_];
__device__ __align__(128) __nv_bfloat16 g_w2lo[H_ * H_];
__device__ __align__(128) float g_dotp[NPART * M_];

// ---------------------------------------------------------------------------
// Helpers
// ---------------------------------------------------------------------------
// byte offset of element (r, k) inside a tile (k in 0..31)
__device__ __forceinline__ uint32_t tile_off(int r, int k)
{
    const uint32_t c = (uint32_t)(k >> 3) & 3;
    const uint32_t x = ((uint32_t)r >> 1) & 3;
    return (uint32_t)(r * 64) + (((c ^ x) & 3) << 4) + (uint32_t)((k & 7) * 2);
}

__device__ __forceinline__ void bulk_g2s(uint32_t dst, const void* src,
                                         uint32_t bytes, uint32_t mbar)
{
    asm volatile(
        "cp.async.bulk.shared::cluster.global.mbarrier::complete_tx::bytes "
        "[%0], [%1], %2, [%3];\n"
        :: "r"(dst), "l"(src), "r"(bytes), "r"(mbar) : "memory");
}

__device__ __forceinline__ void mbar_init(uint32_t addr, uint32_t cnt)
{
    asm volatile("mbarrier.init.shared.b64 [%0], %1;" :: "r"(addr), "r"(cnt) : "memory");
}

__device__ __forceinline__ void mbar_expect_tx(uint32_t addr, uint32_t bytes)
{
    asm volatile("mbarrier.arrive.expect_tx.shared.b64 _, [%0], %1;"
                 :: "r"(addr), "r"(bytes) : "memory");
}

__device__ __forceinline__ void mbar_wait(uint32_t addr, uint32_t parity)
{
    asm volatile(
        "{\n\t.reg .pred P;\n"
        "W_%=:\n\t"
        "mbarrier.try_wait.parity.acquire.cta.shared::cta.b64 P, [%0], %1, 0x989680;\n\t"
        "@P bra D_%=;\n\t"
        "bra W_%=;\n"
        "D_%=:\n\t}"
        :: "r"(addr), "r"(parity) : "memory");
}

__device__ __forceinline__ void ldsm_x4(uint32_t* r, uint32_t addr)
{
    asm volatile("ldmatrix.sync.aligned.m8n8.x4.shared.b16 {%0,%1,%2,%3}, [%4];"
                 : "=r"(r[0]), "=r"(r[1]), "=r"(r[2]), "=r"(r[3]) : "r"(addr));
}

__device__ __forceinline__ void mma_bf16(float* d, const uint32_t* a,
                                         uint32_t b0, uint32_t b1)
{
    asm volatile(
        "mma.sync.aligned.m16n8k16.row.col.f32.bf16.bf16.f32 "
        "{%0,%1,%2,%3}, {%4,%5,%6,%7}, {%8,%9}, {%0,%1,%2,%3};"
        : "+f"(d[0]), "+f"(d[1]), "+f"(d[2]), "+f"(d[3])
        : "r"(a[0]), "r"(a[1]), "r"(a[2]), "r"(a[3]), "r"(b0), "r"(b1));
}

__device__ __forceinline__ float gelu_exact(float x)
{
    return 0.5f * x * (1.0f + erff(x * 0.70710678118654752f));
}

__device__ __forceinline__ void split_bf16(float v, __nv_bfloat16& h, __nv_bfloat16& l)
{
    h = __float2bfloat16(v);
    l = __float2bfloat16(v - __bfloat162float(h));
}

// ---------------------------------------------------------------------------
// Kernel 1: per-(batch, statement) mean pooling -> split bf16, TILED layout.
// ---------------------------------------------------------------------------
__global__ __launch_bounds__(256) void pool_kernel(const float* __restrict__ hidden,
                                                   const int*   __restrict__ sids)
{
    const int bs = blockIdx.x;
    const int b  = bs >> 7;
    const int s  = bs & (S_ - 1);

    __shared__ int s_lo, s_hi;
    if (threadIdx.x == 0) {
        const int* ids = sids + b * T_;
        int lo = 0, hi = T_;
        while (lo < hi) { int m = (lo + hi) >> 1; if (ids[m] < s) lo = m + 1; else hi = m; }
        s_lo = lo;
        hi = T_;
        while (lo < hi) { int m = (lo + hi) >> 1; if (ids[m] < s + 1) lo = m + 1; else hi = m; }
        s_hi = lo;
    }
    __syncthreads();

    const int lo  = s_lo;
    const int cnt = s_hi - s_lo;
    const float inv = 1.0f / (float)max(cnt, 1);

    const int c = threadIdx.x;
    float a0 = 0.f, a1 = 0.f, a2 = 0.f;
    const float* row = hidden + ((size_t)b * T_ + lo) * H_;
    for (int t = 0; t < cnt; ++t, row += H_) {
        a0 += row[c];
        a1 += row[c + 256];
        a2 += row[c + 512];
    }
    const int mblk = bs >> 7;
    const int r    = bs & 127;
    float v[3] = { a0 * inv, a1 * inv, a2 * inv };
#pragma unroll
    for (int j = 0; j < 3; ++j) {
        const int col = c + j * 256;
        const size_t idx = ((size_t)(mblk * NKCH + (col >> 5)) << 12)
                         + (tile_off(r, col & 31) >> 1);
        __nv_bfloat16 h, l;
        split_bf16(v[j], h, l);
        g_ahi[idx] = h;
        g_alo[idx] = l;
    }
}

// ---------------------------------------------------------------------------
// Kernel 2: weight transpose + bf16 split into TILED layout (192-row tiles).
// ---------------------------------------------------------------------------
__global__ __launch_bounds__(256) void wsplit_kernel(const float* __restrict__ W,
                                                     int which)
{
    __nv_bfloat16* hi = which ? g_w2hi : g_w1hi;
    __nv_bfloat16* lo = which ? g_w2lo : g_w1lo;

    __shared__ float tile[32][33];
    const int kb = blockIdx.y * 32, nb = blockIdx.x * 32;
    const int tx = threadIdx.x, ty = threadIdx.y;   // 32 x 8

#pragma unroll
    for (int i = ty; i < 32; i += 8)
        tile[i][tx] = W[(size_t)(kb + i) * H_ + nb + tx];
    __syncthreads();
    const int kch = kb >> 5;                        // k-chunk for this block
#pragma unroll
    for (int i = ty; i < 32; i += 8) {
        const float v = tile[tx][i];                // W[kb+tx][nb+i]
        const int n = nb + i;
        const int nblk = n / BN, r = n % BN;        // 192-row tiles
        const size_t idx = (size_t)(nblk * NKCH + kch) * (B_T / 2)
                         + (tile_off(r, tx) >> 1);
        __nv_bfloat16 h, l;
        split_bf16(v, h, l);
        hi[idx] = h;
        lo[idx] = l;
    }
}

// ---------------------------------------------------------------------------
// Kernel 3: fused split-bf16 mma.sync GEMM + bias + exact GELU.
//   acc += Ahi.Bhi + Alo.Bhi + Ahi.Blo  (drops only Alo.Blo ~2^-16 rel)
// Stages loaded with 4 cp.async.bulk per chunk (mbarrier complete_tx) from
// pre-tiled, pre-swizzled gmem. CTA 128x192, 8 warps of 32x96, 2 stages.
// MODE 0: A=g_ahi/g_alo, B=g_w1*, out split bf16 -> g_xhi/g_xlo (tiled).
// MODE 1: A=g_xhi/g_xlo, B=g_w2*, fused head: gelu -> dot w3 -> g_dotp.
// ---------------------------------------------------------------------------
template <int MODE>
__global__ __launch_bounds__(256, 2) void gemm_mma_kernel(const float* __restrict__ bias,
                                                          const float* __restrict__ w3)
{
    const char* __restrict__ Ahi = (const char*)(MODE ? g_xhi : g_ahi);
    const char* __restrict__ Alo = (const char*)(MODE ? g_xlo : g_alo);
    const char* __restrict__ Bhi = (const char*)(MODE ? g_w2hi : g_w1hi);
    const char* __restrict__ Blo = (const char*)(MODE ? g_w2lo : g_w1lo);

    extern __shared__ __align__(128) char smem[];
    const uint32_t sb = (uint32_t)__cvta_generic_to_shared(smem);
    const uint32_t mbw = sb + DATA_B;             // 2 mbarriers at +0, +8

    const int tid  = threadIdx.x;
    const int wid  = tid >> 5;
    const int lane = tid & 31;
    const int gid  = lane >> 2;
    const int tig  = lane & 3;
    const int m0 = blockIdx.y * BM;
    const int n0 = blockIdx.x * BN;

    if (tid == 0) {
        mbar_init(mbw, 1);
        mbar_init(mbw + 8, 1);
    }
    __syncthreads();

    auto issue = [&](int c) {                      // tid 0 only
        const int s = c & 1;
        const uint32_t base = sb + s * STAGE_B;
        const uint32_t mb = mbw + s * 8;
        mbar_expect_tx(mb, STAGE_B);
        const size_t at = (size_t)(blockIdx.y * NKCH + c) * A_T;
        const size_t bt = (size_t)(blockIdx.x * NKCH + c) * B_T;
        bulk_g2s(base + OFF_AHI, Ahi + at, A_T, mb);
        bulk_g2s(base + OFF_ALO, Alo + at, A_T, mb);
        bulk_g2s(base + OFF_BHI, Bhi + bt, B_T, mb);
        bulk_g2s(base + OFF_BLO, Blo + bt, B_T, mb);
    };

    // warp tile: 32 (m) x 96 (n);  8 warps = 4m x 2n
    const int wm = (wid & 3) * 32;
    const int wn = (wid >> 2) * 96;

    // ldmatrix lane addressing (audited R12 mapping): lm_row = lane&15 rows,
    // lm_col = (lane>>4)*16 byte column -> regs a0..a3 in PTX fragment order.
    // Swizzle xor term is a per-lane constant: (r>>1)&3 == (lm_row>>1)&3
    // because wm/wn/group offsets are multiples of 16.
    const int lm_row = lane & 15;
    const int lm_col = (lane >> 4) & 1;            // 0 or 1 (16B units)
    const uint32_t xsw = ((uint32_t)lm_row >> 1) & 3;
    uint32_t csw[2];                               // swizzled byte-col per kk2
#pragma unroll
    for (int kk2 = 0; kk2 < 2; ++kk2)
        csw[kk2] = ((((uint32_t)(kk2 * 2 + lm_col)) ^ xsw) & 3) << 4;
    const uint32_t a_base = (uint32_t)((wm + lm_row) * 64);
    const uint32_t b_base = (uint32_t)((wn + lm_row) * 64);

    float acc[2][12][4];
#pragma unroll
    for (int i = 0; i < 2; ++i)
#pragma unroll
        for (int j = 0; j < 12; ++j)
#pragma unroll
            for (int k = 0; k < 4; ++k) acc[i][j][k] = 0.f;

    if (tid == 0) { issue(0); issue(1); }

#pragma unroll 1
    for (int c = 0; c < NCH; ++c) {
        const uint32_t st = sb + (c & 1) * STAGE_B;
        mbar_wait(mbw + (c & 1) * 8, (c >> 1) & 1);

#pragma unroll
        for (int kk2 = 0; kk2 < 2; ++kk2) {
            const uint32_t cb = csw[kk2];
            uint32_t ahi[2][4], alo[2][4];
            ldsm_x4(ahi[0], st + OFF_AHI + a_base + cb);
            ldsm_x4(ahi[1], st + OFF_AHI + a_base + 16 * 64 + cb);
            ldsm_x4(alo[0], st + OFF_ALO + a_base + cb);
            ldsm_x4(alo[1], st + OFF_ALO + a_base + 16 * 64 + cb);
#pragma unroll
            for (int g = 0; g < 6; ++g) {          // n-groups of 16
                uint32_t bh[4], bl[4];
                ldsm_x4(bh, st + OFF_BHI + b_base + (uint32_t)(g * 16 * 64) + cb);
                ldsm_x4(bl, st + OFF_BLO + b_base + (uint32_t)(g * 16 * 64) + cb);
                // product-major order (RAW chain distance 4)
                mma_bf16(acc[0][2 * g],     ahi[0], bh[0], bh[2]);
                mma_bf16(acc[0][2 * g + 1], ahi[0], bh[1], bh[3]);
                mma_bf16(acc[1][2 * g],     ahi[1], bh[0], bh[2]);
                mma_bf16(acc[1][2 * g + 1], ahi[1], bh[1], bh[3]);

                mma_bf16(acc[0][2 * g],     alo[0], bh[0], bh[2]);
                mma_bf16(acc[0][2 * g + 1], alo[0], bh[1], bh[3]);
                mma_bf16(acc[1][2 * g],     alo[1], bh[0], bh[2]);
                mma_bf16(acc[1][2 * g + 1], alo[1], bh[1], bh[3]);

                mma_bf16(acc[0][2 * g],     ahi[0], bl[0], bl[2]);
                mma_bf16(acc[0][2 * g + 1], ahi[0], bl[1], bl[3]);
                mma_bf16(acc[1][2 * g],     ahi[1], bl[0], bl[2]);
                mma_bf16(acc[1][2 * g + 1], ahi[1], bl[1], bl[3]);
            }
        }
        __syncthreads();                            // all readers done with stage
        if (c + 2 < NCH && tid == 0) issue(c + 2);  // safe to overwrite it
    }

    // Epilogue: PTX C layout: c0/c1 at (gid, tig*2 /+1), c2/c3 at (gid+8, ...)
#pragma unroll
    for (int mt = 0; mt < 2; ++mt) {
        const int rin = wm + mt * 16 + gid;        // row within 128-row tile
        float d0 = 0.f, d1 = 0.f;                  // MODE 1 head partials
#pragma unroll
        for (int nt = 0; nt < 12; ++nt) {
            const int col = n0 + wn + nt * 8 + tig * 2;
            const float bz0 = __ldg(&bias[col]);
            const float bz1 = __ldg(&bias[col + 1]);
            const float* a4 = acc[mt][nt];
            const float v00 = gelu_exact(a4[0] + bz0);
            const float v01 = gelu_exact(a4[1] + bz1);
            const float v10 = gelu_exact(a4[2] + bz0);
            const float v11 = gelu_exact(a4[3] + bz1);
            if (MODE == 0) {
                // write into the TILED A-layout that gemm<1> bulk-loads
                const int kch = col >> 5, kin = col & 31;
                const size_t t0 = ((size_t)(blockIdx.y * NKCH + kch) << 12)
                                + (tile_off(rin, kin) >> 1);
                const size_t t1 = ((size_t)(blockIdx.y * NKCH + kch) << 12)
                                + (tile_off(rin + 8, kin) >> 1);
                __nv_bfloat162 h0, l0, h1, l1;
                split_bf16(v00, h0.x, l0.x); split_bf16(v01, h0.y, l0.y);
                split_bf16(v10, h1.x, l1.x); split_bf16(v11, h1.y, l1.y);
                *(__nv_bfloat162*)((__nv_bfloat16*)g_xhi + t0) = h0;
                *(__nv_bfloat162*)((__nv_bfloat16*)g_xlo + t0) = l0;
                *(__nv_bfloat162*)((__nv_bfloat16*)g_xhi + t1) = h1;
                *(__nv_bfloat162*)((__nv_bfloat16*)g_xlo + t1) = l1;
            } else {
                const float w0 = __ldg(&w3[col]);
                const float w1 = __ldg(&w3[col + 1]);
                d0 += v00 * w0 + v01 * w1;
                d1 += v10 * w0 + v11 * w1;
            }
        }
        if (MODE == 1) {
            d0 += __shfl_xor_sync(0xffffffffu, d0, 1);
            d0 += __shfl_xor_sync(0xffffffffu, d0, 2);
            d1 += __shfl_xor_sync(0xffffffffu, d1, 1);
            d1 += __shfl_xor_sync(0xffffffffu, d1, 2);
            if (tig == 0) {
                const int p = blockIdx.x * 2 + (wid >> 2);   // 0..7
                const int r0 = m0 + rin;
                g_dotp[p * M_ + r0]     = d0;
                g_dotp[p * M_ + r0 + 8] = d1;
            }
        }
    }
}

// ---------------------------------------------------------------------------
// Kernel 4: out[i] = sigmoid(sum_p dotp[p][i] + b3).  Deterministic partials.
// ---------------------------------------------------------------------------
__global__ __launch_bounds__(256) void finalize_kernel(const float* __restrict__ b3,
                                                       float* __restrict__ out)
{
    const int i = blockIdx.x * 256 + threadIdx.x;
    float s = b3[0];
#pragma unroll
    for (int p = 0; p < NPART; ++p) s += g_dotp[p * M_ + i];
    out[i] = 1.0f / (1.0f + expf(-s));
}

// ---------------------------------------------------------------------------
// Launch: wsplit(w1,w2) -> pool -> gemm<0> -> gemm<1> (fused head) -> finalize.
// Only harness d_in/d_out pointers cross the host boundary; all scratch is
// device-side symbols. Graph-capturable, allocation-free.
// ---------------------------------------------------------------------------
extern "C" void kernel_launch(void* const* d_in, const int* in_sizes, int n_in,
                              void* d_out, int out_size)
{
    const float* hidden = (const float*)d_in[0];
    const int*   sids   = (const int*)  d_in[1];
    const float* w1     = (const float*)d_in[2];
    const float* b1     = (const float*)d_in[3];
    const float* w2     = (const float*)d_in[4];
    const float* b2     = (const float*)d_in[5];
    const float* w3     = (const float*)d_in[6];
    const float* b3     = (const float*)d_in[7];
    float*       out    = (float*)d_out;

    cudaFuncSetAttribute(gemm_mma_kernel<0>,
                         cudaFuncAttributeMaxDynamicSharedMemorySize, SMEM_B);
    cudaFuncSetAttribute(gemm_mma_kernel<1>,
                         cudaFuncAttributeMaxDynamicSharedMemorySize, SMEM_B);

    dim3 wgrid(H_ / 32, H_ / 32);     // (24, 24)
    dim3 wblk(32, 8);
    wsplit_kernel<<<wgrid, wblk>>>(w1, 0);
    wsplit_kernel<<<wgrid, wblk>>>(w2, 1);

    pool_kernel<<<M_, 256>>>(hidden, sids);            // -> g_ahi / g_alo (tiled)

    dim3 grid(H_ / BN, M_ / BM);                        // (4, 64) = 256 CTAs
    gemm_mma_kernel<0><<<grid, 256, SMEM_B>>>(b1, w3);  // -> g_xhi / g_xlo (tiled)
    gemm_mma_kernel<1><<<grid, 256, SMEM_B>>>(b2, w3);  // -> g_dotp

    finalize_kernel<<<M_ / 256, 256>>>(b3, out);        // g_dotp -> out
}